// round 9
// baseline (speedup 1.0000x reference)
#include <cuda_runtime.h>
#include <cuda_fp16.h>
#include <cstdint>

// ---------------- problem constants ----------------
#define NB   8
#define NL   1024
#define NH   8
#define NE   64
#define HIST 512
#define SCALE 0.125f
#define CEXP  0.1803368801111244f   // SCALE * log2(e)
#define ROWSTRIDE 512               // NH * NE

#define BQ   128             // query rows per CTA
#define TKV  64              // keys per tile
#define NTHREADS 256         // 8 warps

// ---------------- smem layout ----------------
// Q fp16 hi/lo: 2 x 16KB. K/V fp16 hi panels double-buffered: 2 x 16KB.
// fp32 cp.async staging (K 16KB + V 16KB) double-buffered: 2 x 32KB.
#define OFF_QHI 0
#define OFF_QLO 16384
#define BFB(s)  (32768 + (s) * 16384)   // +0 K hi (8KB), +8192 V hi (8KB)
#define STG(s)  (65536 + (s) * 32768)   // +0 K fp32, +16384 V fp32
#define SMEM_TOTAL 131072

__device__ __forceinline__ uint32_t swz(uint32_t x) { return x ^ ((x >> 3) & 0x70); }

__device__ __forceinline__ uint32_t smem_u32(const void* p) {
    uint32_t a;
    asm("{ .reg .u64 t; cvta.to.shared.u64 t, %1; cvt.u32.u64 %0, t; }" : "=r"(a) : "l"(p));
    return a;
}

__device__ __forceinline__ void ldsm4(uint32_t& r0, uint32_t& r1, uint32_t& r2, uint32_t& r3, uint32_t a) {
    asm volatile("ldmatrix.sync.aligned.m8n8.x4.shared.b16 {%0,%1,%2,%3}, [%4];"
                 : "=r"(r0), "=r"(r1), "=r"(r2), "=r"(r3) : "r"(a));
}
__device__ __forceinline__ void ldsm4t(uint32_t& r0, uint32_t& r1, uint32_t& r2, uint32_t& r3, uint32_t a) {
    asm volatile("ldmatrix.sync.aligned.m8n8.x4.trans.shared.b16 {%0,%1,%2,%3}, [%4];"
                 : "=r"(r0), "=r"(r1), "=r"(r2), "=r"(r3) : "r"(a));
}

// pack two fp32 -> fp16x2 (x -> low half, y -> high half)
__device__ __forceinline__ uint32_t packh(float x, float y) {
    __half2 h = __floats2half2_rn(x, y);
    return *reinterpret_cast<uint32_t*>(&h);
}

// split pair into fp16 hi word + fp16 residual word
__device__ __forceinline__ void splith_pair(float x, float y, uint32_t& hp, uint32_t& lp) {
    __half2 h = __floats2half2_rn(x, y);
    hp = *reinterpret_cast<uint32_t*>(&h);
    lp = packh(x - __low2float(h), y - __high2float(h));
}

__device__ __forceinline__ void mma_f16(float* c, uint32_t a0, uint32_t a1, uint32_t a2, uint32_t a3,
                                        uint32_t b0, uint32_t b1) {
    asm volatile(
        "mma.sync.aligned.m16n8k16.row.col.f32.f16.f16.f32 "
        "{%0,%1,%2,%3}, {%4,%5,%6,%7}, {%8,%9}, {%0,%1,%2,%3};"
        : "+f"(c[0]), "+f"(c[1]), "+f"(c[2]), "+f"(c[3])
        : "r"(a0), "r"(a1), "r"(a2), "r"(a3), "r"(b0), "r"(b1));
}

__device__ __forceinline__ void sts32(uint32_t addr, uint32_t v) {
    asm volatile("st.shared.b32 [%0], %1;" :: "r"(addr), "r"(v) : "memory");
}
__device__ __forceinline__ void sts64(uint32_t addr, uint32_t a, uint32_t b) {
    asm volatile("st.shared.v2.b32 [%0], {%1,%2};" :: "r"(addr), "r"(a), "r"(b) : "memory");
}
__device__ __forceinline__ void lds128(float& x, float& y, float& z, float& w, uint32_t addr) {
    asm volatile("ld.shared.v4.f32 {%0,%1,%2,%3}, [%4];"
                 : "=f"(x), "=f"(y), "=f"(z), "=f"(w) : "r"(addr));
}
__device__ __forceinline__ void cpasync16(uint32_t saddr, const void* gaddr) {
    asm volatile("cp.async.cg.shared.global [%0], [%1], 16;" :: "r"(saddr), "l"(gaddr));
}

__global__ __launch_bounds__(NTHREADS, 1)
void ftc_attn_mma(const float* __restrict__ Q, const float* __restrict__ K,
                  const float* __restrict__ V, const float* __restrict__ QD,
                  const float* __restrict__ KD, const float* __restrict__ VD,
                  float* __restrict__ Out)
{
    extern __shared__ char smem[];
    const uint32_t sb = smem_u32(smem);
    const int tid  = threadIdx.x;
    const int w    = tid >> 5;
    const int lane = tid & 31;
    const int g    = lane >> 2;
    const int tig  = lane & 3;

    // LPT schedule: strictly descending work
    const int bid = blockIdx.x;
    const int qt  = 7 - (bid >> 6);
    const int hb  = bid & 63;
    const int h   = hb & 7;
    const int b   = hb >> 3;
    const size_t base = (size_t)b * NL * ROWSTRIDE + (size_t)h * NE;
    const bool drawn = (qt >= HIST / BQ);

    const int r0 = 8 * g + w;            // warp w owns tile rows {8i + w}
    const int l0 = qt * BQ + r0;
    const int l1 = l0 + 64;
    const int ntiles = 2 * qt + 2;

    // ---- cp.async prefetch of tiles 0,1 ----
    auto prefetch_async = [&](int t, int s) {
        const int s0 = t * TKV;
        const float* kbp = K + base + (size_t)s0 * ROWSTRIDE;
        const float* vbp = V + base + (size_t)s0 * ROWSTRIDE;
        const uint32_t stg = sb + STG(s);
        #pragma unroll
        for (int i = 0; i < 4; i++) {
            int idx = i * NTHREADS + tid;
            int r = idx >> 4, c4 = idx & 15;
            cpasync16(stg + idx * 16,         kbp + (size_t)r * ROWSTRIDE + c4 * 4);
            cpasync16(stg + 16384 + idx * 16, vbp + (size_t)r * ROWSTRIDE + c4 * 4);
        }
        asm volatile("cp.async.commit_group;" ::: "memory");
    };
    prefetch_async(0, 0);
    prefetch_async(1, 1);

    // ---- load + split Q tile (fp16 hi + residual) into permuted smem rows ----
    const float* qsrc = drawn ? QD : Q;
    #pragma unroll
    for (int i = 0; i < 16; i++) {
        int idx = i * NTHREADS + tid;
        int r = idx >> 5, cp = idx & 31;
        float2 v = *(const float2*)(qsrc + base + (size_t)(qt * BQ + r) * ROWSTRIDE + cp * 2);
        int srow = (r & 7) * 16 + (r >> 3);
        uint32_t o = swz(srow * 128 + cp * 4);
        uint32_t hp, lp;
        splith_pair(v.x, v.y, hp, lp);
        sts32(sb + OFF_QHI + o, hp);
        sts32(sb + OFF_QLO + o, lp);
    }

    // ---- exact fp32 diag scores (drawn rows) ----
    float dd0s = 0.0f, dd1s = 0.0f;
    if (drawn) {
        float d0 = 0.0f, d1 = 0.0f;
        const float* qd0 = QD + base + (size_t)l0 * ROWSTRIDE + tig * 16;
        const float* kd0 = KD + base + (size_t)l0 * ROWSTRIDE + tig * 16;
        const float* qd1 = QD + base + (size_t)l1 * ROWSTRIDE + tig * 16;
        const float* kd1 = KD + base + (size_t)l1 * ROWSTRIDE + tig * 16;
        #pragma unroll
        for (int i = 0; i < 4; i++) {
            float4 a = *(const float4*)(qd0 + i * 4), c = *(const float4*)(kd0 + i * 4);
            d0 = fmaf(a.x, c.x, d0); d0 = fmaf(a.y, c.y, d0);
            d0 = fmaf(a.z, c.z, d0); d0 = fmaf(a.w, c.w, d0);
            float4 e = *(const float4*)(qd1 + i * 4), f = *(const float4*)(kd1 + i * 4);
            d1 = fmaf(e.x, f.x, d1); d1 = fmaf(e.y, f.y, d1);
            d1 = fmaf(e.z, f.z, d1); d1 = fmaf(e.w, f.w, d1);
        }
        d0 += __shfl_xor_sync(0xffffffffu, d0, 1);
        d0 += __shfl_xor_sync(0xffffffffu, d0, 2);
        d1 += __shfl_xor_sync(0xffffffffu, d1, 1);
        d1 += __shfl_xor_sync(0xffffffffu, d1, 2);
        dd0s = d0 * CEXP;
        dd1s = d1 * CEXP;
    }

    // ---- commit: staged fp32 -> fp16 hi panels (convert only, no residual) ----
    auto commit_tile = [&](int s) {
        const uint32_t stg = sb + STG(s);
        const uint32_t kh = sb + BFB(s), vh = kh + 8192;
        #pragma unroll
        for (int i = 0; i < 4; i++) {
            int idx = i * NTHREADS + tid;
            int r = idx >> 4, c4 = idx & 15;
            uint32_t dsw = swz((uint32_t)(r * 128 + c4 * 8));
            float kx, ky, kz, kw, vx, vy, vz, vw;
            lds128(kx, ky, kz, kw, stg + idx * 16);
            lds128(vx, vy, vz, vw, stg + 16384 + idx * 16);
            sts64(kh + dsw, packh(kx, ky), packh(kz, kw));
            sts64(vh + dsw, packh(vx, vy), packh(vz, vw));
        }
    };

    // per-lane ldmatrix address parts
    const uint32_t srowA_byte = (uint32_t)(w * 16 + ((lane >> 3) & 1) * 8 + (lane & 7)) * 128;
    const uint32_t cbA_half   = (uint32_t)((lane >> 4) & 1) * 16;
    const uint32_t rowB = ((lane >> 4) & 1) * 8 + (lane & 7);
    const uint32_t colB = ((lane >> 3) & 1) * 16;
    const uint32_t rowV = ((lane >> 3) & 1) * 8 + (lane & 7);
    const uint32_t colV = ((lane >> 4) & 1) * 16;

    float o_[8][4];
    #pragma unroll
    for (int nb = 0; nb < 8; nb++)
        #pragma unroll
        for (int e = 0; e < 4; e++) o_[nb][e] = 0.0f;
    float lsum0 = 0.0f, lsum1 = 0.0f, pd0 = 0.0f, pd1 = 0.0f;

    asm volatile("cp.async.wait_group 1;" ::: "memory");
    commit_tile(0);
    __syncthreads();

    // ---- hoist Q fragments (tile-invariant) ----
    uint32_t qh[4][4], ql[4][4];
    #pragma unroll
    for (int ks = 0; ks < 4; ks++) {
        uint32_t aoff = swz(srowA_byte + ks * 32 + cbA_half);
        ldsm4(qh[ks][0], qh[ks][1], qh[ks][2], qh[ks][3], sb + OFF_QHI + aoff);
        ldsm4(ql[ks][0], ql[ks][1], ql[ks][2], ql[ks][3], sb + OFF_QLO + aoff);
    }

    for (int t = 0; t < ntiles; t++) {
        const int cur = t & 1;
        const uint32_t khb = sb + BFB(cur);
        const uint32_t vhb = khb + 8192;

        // ---- QK: S = (Qh + Ql) . Kh^T (2 terms) ----
        float c_[8][4];
        #pragma unroll
        for (int nb = 0; nb < 8; nb++)
            #pragma unroll
            for (int e = 0; e < 4; e++) c_[nb][e] = 0.0f;

        #pragma unroll
        for (int ks = 0; ks < 4; ks++) {
            #pragma unroll
            for (int nbP = 0; nbP < 4; nbP++) {
                uint32_t boff = swz((uint32_t)(nbP * 16 + rowB) * 128 + ks * 32 + colB);
                uint32_t bh0, bh1, bh2, bh3;
                ldsm4(bh0, bh1, bh2, bh3, khb + boff);
                mma_f16(c_[2 * nbP],     qh[ks][0], qh[ks][1], qh[ks][2], qh[ks][3], bh0, bh1);
                mma_f16(c_[2 * nbP + 1], qh[ks][0], qh[ks][1], qh[ks][2], qh[ks][3], bh2, bh3);
                mma_f16(c_[2 * nbP],     ql[ks][0], ql[ks][1], ql[ks][2], ql[ks][3], bh0, bh1);
                mma_f16(c_[2 * nbP + 1], ql[ks][0], ql[ks][1], ql[ks][2], ql[ks][3], bh2, bh3);
            }
        }

        // ---- commit next tile's fp16 panels while QK HMMAs drain ----
        if (t + 1 < ntiles) {
            asm volatile("cp.async.wait_group 0;" ::: "memory");
            commit_tile((t + 1) & 1);
        }

        // ---- softmax chunk interleaved with PV k-step ----
        const bool full = (t < 2 * qt);
        const int s0t = t * TKV;
        #pragma unroll
        for (int ks = 0; ks < 4; ks++) {
            uint32_t a0, a1, a2, a3, q0, q1, q2, q3;
            #pragma unroll
            for (int half = 0; half < 2; half++) {
                const int nb = 2 * ks + half;
                float p0, p1, p2, p3;
                if (full) {
                    p0 = exp2f(c_[nb][0] * CEXP);
                    p1 = exp2f(c_[nb][1] * CEXP);
                    p2 = exp2f(c_[nb][2] * CEXP);
                    p3 = exp2f(c_[nb][3] * CEXP);
                } else {
                    const int colA = s0t + nb * 8 + 2 * tig;
                    const int colBc = colA + 1;
                    float s0f = c_[nb][0] * CEXP, s1f = c_[nb][1] * CEXP;
                    float s2f = c_[nb][2] * CEXP, s3f = c_[nb][3] * CEXP;
                    if (drawn) {
                        if (colA == l0)  s0f = dd0s;
                        if (colBc == l0) s1f = dd0s;
                        if (colA == l1)  s2f = dd1s;
                        if (colBc == l1) s3f = dd1s;
                    }
                    p0 = (colA <= l0)  ? exp2f(s0f) : 0.0f;
                    p1 = (colBc <= l0) ? exp2f(s1f) : 0.0f;
                    p2 = (colA <= l1)  ? exp2f(s2f) : 0.0f;
                    p3 = (colBc <= l1) ? exp2f(s3f) : 0.0f;
                    if (drawn) {
                        if (colA == l0)  pd0 = p0;
                        if (colBc == l0) pd0 = p1;
                        if (colA == l1)  pd1 = p2;
                        if (colBc == l1) pd1 = p3;
                    }
                }
                lsum0 += p0 + p1; lsum1 += p2 + p3;
                if (half == 0) { splith_pair(p0, p1, a0, q0); splith_pair(p2, p3, a1, q1); }
                else           { splith_pair(p0, p1, a2, q2); splith_pair(p2, p3, a3, q3); }
            }
            #pragma unroll
            for (int nbP = 0; nbP < 4; nbP++) {
                uint32_t voff = swz((uint32_t)(ks * 16 + rowV) * 128 + nbP * 32 + colV);
                uint32_t vh0, vh1, vh2, vh3;
                ldsm4t(vh0, vh1, vh2, vh3, vhb + voff);
                mma_f16(o_[2 * nbP],     a0, a1, a2, a3, vh0, vh1);
                mma_f16(o_[2 * nbP + 1], a0, a1, a2, a3, vh2, vh3);
                mma_f16(o_[2 * nbP],     q0, q1, q2, q3, vh0, vh1);
                mma_f16(o_[2 * nbP + 1], q0, q1, q2, q3, vh2, vh3);
            }
        }

        __syncthreads();
        if (t + 2 < ntiles) prefetch_async(t + 2, t & 1);
    }

    // ---- quad reductions ----
    lsum0 += __shfl_xor_sync(0xffffffffu, lsum0, 1);
    lsum0 += __shfl_xor_sync(0xffffffffu, lsum0, 2);
    lsum1 += __shfl_xor_sync(0xffffffffu, lsum1, 1);
    lsum1 += __shfl_xor_sync(0xffffffffu, lsum1, 2);
    pd0 += __shfl_xor_sync(0xffffffffu, pd0, 1);
    pd0 += __shfl_xor_sync(0xffffffffu, pd0, 2);
    pd1 += __shfl_xor_sync(0xffffffffu, pd1, 1);
    pd1 += __shfl_xor_sync(0xffffffffu, pd1, 2);
    const float inv0 = 1.0f / lsum0;
    const float inv1 = 1.0f / lsum1;

    // ---- epilogue ----
    float* o0p = Out + base + (size_t)l0 * ROWSTRIDE;
    float* o1p = Out + base + (size_t)l1 * ROWSTRIDE;
    if (drawn) {
        const float* v0  = V  + base + (size_t)l0 * ROWSTRIDE;
        const float* vd0 = VD + base + (size_t)l0 * ROWSTRIDE;
        const float* v1  = V  + base + (size_t)l1 * ROWSTRIDE;
        const float* vd1 = VD + base + (size_t)l1 * ROWSTRIDE;
        #pragma unroll
        for (int nb = 0; nb < 8; nb++) {
            int e = nb * 8 + 2 * tig;
            float2 vv = *(const float2*)(v0 + e);
            float2 vd = *(const float2*)(vd0 + e);
            float2 out;
            out.x = (o_[nb][0] + pd0 * (vd.x - vv.x)) * inv0;
            out.y = (o_[nb][1] + pd0 * (vd.y - vv.y)) * inv0;
            *(float2*)(o0p + e) = out;
            float2 vv1  = *(const float2*)(v1 + e);
            float2 vd1v = *(const float2*)(vd1 + e);
            float2 out1;
            out1.x = (o_[nb][2] + pd1 * (vd1v.x - vv1.x)) * inv1;
            out1.y = (o_[nb][3] + pd1 * (vd1v.y - vv1.y)) * inv1;
            *(float2*)(o1p + e) = out1;
        }
    } else {
        #pragma unroll
        for (int nb = 0; nb < 8; nb++) {
            int e = nb * 8 + 2 * tig;
            float2 out;
            out.x = o_[nb][0] * inv0;
            out.y = o_[nb][1] * inv0;
            *(float2*)(o0p + e) = out;
            float2 out1;
            out1.x = o_[nb][2] * inv1;
            out1.y = o_[nb][3] * inv1;
            *(float2*)(o1p + e) = out1;
        }
    }
}

extern "C" void kernel_launch(void* const* d_in, const int* in_sizes, int n_in,
                              void* d_out, int out_size)
{
    const float* Q  = (const float*)d_in[0];
    const float* K  = (const float*)d_in[1];
    const float* V  = (const float*)d_in[2];
    const float* QD = (const float*)d_in[3];
    const float* KD = (const float*)d_in[4];
    const float* VD = (const float*)d_in[5];
    float* O = (float*)d_out;

    static int configured = 0;
    if (!configured) {
        cudaFuncSetAttribute(ftc_attn_mma, cudaFuncAttributeMaxDynamicSharedMemorySize, SMEM_TOTAL);
        configured = 1;
    }
    ftc_attn_mma<<<512, NTHREADS, SMEM_TOTAL>>>(Q, K, V, QD, KD, VD, O);
}

// round 13
// speedup vs baseline: 1.4081x; 1.4081x over previous
#include <cuda_runtime.h>
#include <cuda_bf16.h>
#include <cuda_fp16.h>
#include <cstdint>

// ---------------- problem constants ----------------
#define NB   8
#define NL   1024
#define NH   8
#define NE   64
#define HIST 512
#define SCALE 0.125f
#define CEXP  0.1803368801111244f   // SCALE * log2(e)
#define ROWSTRIDE 512               // NH * NE

#define BQ   128             // query rows per CTA
#define TKV  64              // keys per tile
#define NTHREADS 256         // 8 warps

// ---------------- smem layout ----------------
// Q bf16 hi/lo: 2 x 16KB.
// Per stage: K bf16 hi (8KB) + K bf16 lo (8KB) + V fp16 (8KB) = 24KB, x2 stages.
// fp32 cp.async staging (K 16KB + V 16KB) x2 stages.
#define OFF_QHI 0
#define OFF_QLO 16384
#define BFB(s)  (32768 + (s) * 24576)   // +0 K hi, +8192 K lo, +16384 V fp16
#define STG(s)  (81920 + (s) * 32768)   // +0 K fp32, +16384 V fp32
#define SMEM_TOTAL 147456

__device__ __forceinline__ uint32_t swz(uint32_t x) { return x ^ ((x >> 3) & 0x70); }

__device__ __forceinline__ uint32_t smem_u32(const void* p) {
    uint32_t a;
    asm("{ .reg .u64 t; cvta.to.shared.u64 t, %1; cvt.u32.u64 %0, t; }" : "=r"(a) : "l"(p));
    return a;
}

__device__ __forceinline__ void ldsm4(uint32_t& r0, uint32_t& r1, uint32_t& r2, uint32_t& r3, uint32_t a) {
    asm volatile("ldmatrix.sync.aligned.m8n8.x4.shared.b16 {%0,%1,%2,%3}, [%4];"
                 : "=r"(r0), "=r"(r1), "=r"(r2), "=r"(r3) : "r"(a));
}
__device__ __forceinline__ void ldsm4t(uint32_t& r0, uint32_t& r1, uint32_t& r2, uint32_t& r3, uint32_t a) {
    asm volatile("ldmatrix.sync.aligned.m8n8.x4.trans.shared.b16 {%0,%1,%2,%3}, [%4];"
                 : "=r"(r0), "=r"(r1), "=r"(r2), "=r"(r3) : "r"(a));
}

// pack two fp32 -> bf16x2 (first arg -> low half)
__device__ __forceinline__ uint32_t packbf(float lo, float hi) {
    uint32_t r;
    asm("cvt.rn.bf16x2.f32 %0, %1, %2;" : "=r"(r) : "f"(hi), "f"(lo));
    return r;
}
// split pair into bf16 hi word + exact-residual bf16 lo word
__device__ __forceinline__ void split_pair(float x, float y, uint32_t& hp, uint32_t& lp) {
    hp = packbf(x, y);
    lp = packbf(x - __uint_as_float(hp << 16), y - __uint_as_float(hp & 0xFFFF0000u));
}
// pack two fp32 -> fp16x2 (x -> low half)
__device__ __forceinline__ uint32_t packh(float x, float y) {
    __half2 h = __floats2half2_rn(x, y);
    return *reinterpret_cast<uint32_t*>(&h);
}

__device__ __forceinline__ void mma_bf16(float* c, uint32_t a0, uint32_t a1, uint32_t a2, uint32_t a3,
                                         uint32_t b0, uint32_t b1) {
    asm volatile(
        "mma.sync.aligned.m16n8k16.row.col.f32.bf16.bf16.f32 "
        "{%0,%1,%2,%3}, {%4,%5,%6,%7}, {%8,%9}, {%0,%1,%2,%3};"
        : "+f"(c[0]), "+f"(c[1]), "+f"(c[2]), "+f"(c[3])
        : "r"(a0), "r"(a1), "r"(a2), "r"(a3), "r"(b0), "r"(b1));
}
__device__ __forceinline__ void mma_f16(float* c, uint32_t a0, uint32_t a1, uint32_t a2, uint32_t a3,
                                        uint32_t b0, uint32_t b1) {
    asm volatile(
        "mma.sync.aligned.m16n8k16.row.col.f32.f16.f16.f32 "
        "{%0,%1,%2,%3}, {%4,%5,%6,%7}, {%8,%9}, {%0,%1,%2,%3};"
        : "+f"(c[0]), "+f"(c[1]), "+f"(c[2]), "+f"(c[3])
        : "r"(a0), "r"(a1), "r"(a2), "r"(a3), "r"(b0), "r"(b1));
}

__device__ __forceinline__ void sts32(uint32_t addr, uint32_t v) {
    asm volatile("st.shared.b32 [%0], %1;" :: "r"(addr), "r"(v) : "memory");
}
__device__ __forceinline__ void sts64(uint32_t addr, uint32_t a, uint32_t b) {
    asm volatile("st.shared.v2.b32 [%0], {%1,%2};" :: "r"(addr), "r"(a), "r"(b) : "memory");
}
__device__ __forceinline__ void lds128(float& x, float& y, float& z, float& w, uint32_t addr) {
    asm volatile("ld.shared.v4.f32 {%0,%1,%2,%3}, [%4];"
                 : "=f"(x), "=f"(y), "=f"(z), "=f"(w) : "r"(addr));
}
__device__ __forceinline__ void cpasync16(uint32_t saddr, const void* gaddr) {
    asm volatile("cp.async.cg.shared.global [%0], [%1], 16;" :: "r"(saddr), "l"(gaddr));
}

__global__ __launch_bounds__(NTHREADS, 1)
void ftc_attn_mma(const float* __restrict__ Q, const float* __restrict__ K,
                  const float* __restrict__ V, const float* __restrict__ QD,
                  const float* __restrict__ KD, const float* __restrict__ VD,
                  float* __restrict__ Out)
{
    extern __shared__ char smem[];
    const uint32_t sb = smem_u32(smem);
    const int tid  = threadIdx.x;
    const int w    = tid >> 5;
    const int lane = tid & 31;
    const int g    = lane >> 2;
    const int tig  = lane & 3;

    // LPT schedule: strictly descending work
    const int bid = blockIdx.x;
    const int qt  = 7 - (bid >> 6);
    const int hb  = bid & 63;
    const int h   = hb & 7;
    const int b   = hb >> 3;
    const size_t base = (size_t)b * NL * ROWSTRIDE + (size_t)h * NE;
    const bool drawn = (qt >= HIST / BQ);

    const int r0 = 8 * g + w;            // warp w owns tile rows {8i + w}
    const int l0 = qt * BQ + r0;
    const int l1 = l0 + 64;
    const int ntiles = 2 * qt + 2;

    // ---- cp.async prefetch of tiles 0,1 ----
    auto prefetch_async = [&](int t, int s) {
        const int s0 = t * TKV;
        const float* kbp = K + base + (size_t)s0 * ROWSTRIDE;
        const float* vbp = V + base + (size_t)s0 * ROWSTRIDE;
        const uint32_t stg = sb + STG(s);
        #pragma unroll
        for (int i = 0; i < 4; i++) {
            int idx = i * NTHREADS + tid;
            int r = idx >> 4, c4 = idx & 15;
            cpasync16(stg + idx * 16,         kbp + (size_t)r * ROWSTRIDE + c4 * 4);
            cpasync16(stg + 16384 + idx * 16, vbp + (size_t)r * ROWSTRIDE + c4 * 4);
        }
        asm volatile("cp.async.commit_group;" ::: "memory");
    };
    prefetch_async(0, 0);
    prefetch_async(1, 1);

    // ---- load + split Q tile (bf16 hi/lo) into permuted smem rows ----
    const float* qsrc = drawn ? QD : Q;
    #pragma unroll
    for (int i = 0; i < 16; i++) {
        int idx = i * NTHREADS + tid;
        int r = idx >> 5, cp = idx & 31;
        float2 v = *(const float2*)(qsrc + base + (size_t)(qt * BQ + r) * ROWSTRIDE + cp * 2);
        int srow = (r & 7) * 16 + (r >> 3);
        uint32_t o = swz(srow * 128 + cp * 4);
        uint32_t hp, lp;
        split_pair(v.x, v.y, hp, lp);
        sts32(sb + OFF_QHI + o, hp);
        sts32(sb + OFF_QLO + o, lp);
    }

    // ---- exact fp32 diag scores (drawn rows) ----
    float dd0s = 0.0f, dd1s = 0.0f;
    if (drawn) {
        float d0 = 0.0f, d1 = 0.0f;
        const float* qd0 = QD + base + (size_t)l0 * ROWSTRIDE + tig * 16;
        const float* kd0 = KD + base + (size_t)l0 * ROWSTRIDE + tig * 16;
        const float* qd1 = QD + base + (size_t)l1 * ROWSTRIDE + tig * 16;
        const float* kd1 = KD + base + (size_t)l1 * ROWSTRIDE + tig * 16;
        #pragma unroll
        for (int i = 0; i < 4; i++) {
            float4 a = *(const float4*)(qd0 + i * 4), c = *(const float4*)(kd0 + i * 4);
            d0 = fmaf(a.x, c.x, d0); d0 = fmaf(a.y, c.y, d0);
            d0 = fmaf(a.z, c.z, d0); d0 = fmaf(a.w, c.w, d0);
            float4 e = *(const float4*)(qd1 + i * 4), f = *(const float4*)(kd1 + i * 4);
            d1 = fmaf(e.x, f.x, d1); d1 = fmaf(e.y, f.y, d1);
            d1 = fmaf(e.z, f.z, d1); d1 = fmaf(e.w, f.w, d1);
        }
        d0 += __shfl_xor_sync(0xffffffffu, d0, 1);
        d0 += __shfl_xor_sync(0xffffffffu, d0, 2);
        d1 += __shfl_xor_sync(0xffffffffu, d1, 1);
        d1 += __shfl_xor_sync(0xffffffffu, d1, 2);
        dd0s = d0 * CEXP;
        dd1s = d1 * CEXP;
    }

    // ---- commit: staged fp32 -> K bf16 hi/lo panels + V fp16 panel ----
    auto commit_tile = [&](int s) {
        const uint32_t stg = sb + STG(s);
        const uint32_t kh = sb + BFB(s), kl = kh + 8192, vh = kh + 16384;
        #pragma unroll
        for (int i = 0; i < 4; i++) {
            int idx = i * NTHREADS + tid;
            int r = idx >> 4, c4 = idx & 15;
            uint32_t dsw = swz((uint32_t)(r * 128 + c4 * 8));
            float kx, ky, kz, kw, vx, vy, vz, vw;
            lds128(kx, ky, kz, kw, stg + idx * 16);
            lds128(vx, vy, vz, vw, stg + 16384 + idx * 16);
            uint32_t h01, l01, h23, l23;
            split_pair(kx, ky, h01, l01); split_pair(kz, kw, h23, l23);
            sts64(kh + dsw, h01, h23);
            sts64(kl + dsw, l01, l23);
            sts64(vh + dsw, packh(vx, vy), packh(vz, vw));
        }
    };

    // per-lane ldmatrix address parts
    const uint32_t srowA_byte = (uint32_t)(w * 16 + ((lane >> 3) & 1) * 8 + (lane & 7)) * 128;
    const uint32_t cbA_half   = (uint32_t)((lane >> 4) & 1) * 16;
    const uint32_t rowB = ((lane >> 4) & 1) * 8 + (lane & 7);
    const uint32_t colB = ((lane >> 3) & 1) * 16;
    const uint32_t rowV = ((lane >> 3) & 1) * 8 + (lane & 7);
    const uint32_t colV = ((lane >> 4) & 1) * 16;

    float o_[8][4];
    #pragma unroll
    for (int nb = 0; nb < 8; nb++)
        #pragma unroll
        for (int e = 0; e < 4; e++) o_[nb][e] = 0.0f;
    float lsum0 = 0.0f, lsum1 = 0.0f, pd0 = 0.0f, pd1 = 0.0f;

    asm volatile("cp.async.wait_group 1;" ::: "memory");
    commit_tile(0);
    __syncthreads();

    // ---- hoist Q fragments (tile-invariant) ----
    uint32_t qh[4][4], ql[4][4];
    #pragma unroll
    for (int ks = 0; ks < 4; ks++) {
        uint32_t aoff = swz(srowA_byte + ks * 32 + cbA_half);
        ldsm4(qh[ks][0], qh[ks][1], qh[ks][2], qh[ks][3], sb + OFF_QHI + aoff);
        ldsm4(ql[ks][0], ql[ks][1], ql[ks][2], ql[ks][3], sb + OFF_QLO + aoff);
    }

    for (int t = 0; t < ntiles; t++) {
        const int cur = t & 1;
        const uint32_t khb = sb + BFB(cur), klb = khb + 8192;
        const uint32_t vhb = khb + 16384;

        // ---- QK: S = (Qh+Ql)(Kh+Kl)^T, 3 split terms, bf16 ----
        float c_[8][4];
        #pragma unroll
        for (int nb = 0; nb < 8; nb++)
            #pragma unroll
            for (int e = 0; e < 4; e++) c_[nb][e] = 0.0f;

        #pragma unroll
        for (int ks = 0; ks < 4; ks++) {
            #pragma unroll
            for (int nbP = 0; nbP < 4; nbP++) {
                uint32_t boff = swz((uint32_t)(nbP * 16 + rowB) * 128 + ks * 32 + colB);
                uint32_t bh0, bh1, bh2, bh3, bl0, bl1, bl2, bl3;
                ldsm4(bh0, bh1, bh2, bh3, khb + boff);
                ldsm4(bl0, bl1, bl2, bl3, klb + boff);
                mma_bf16(c_[2 * nbP],     qh[ks][0], qh[ks][1], qh[ks][2], qh[ks][3], bh0, bh1);
                mma_bf16(c_[2 * nbP],     qh[ks][0], qh[ks][1], qh[ks][2], qh[ks][3], bl0, bl1);
                mma_bf16(c_[2 * nbP],     ql[ks][0], ql[ks][1], ql[ks][2], ql[ks][3], bh0, bh1);
                mma_bf16(c_[2 * nbP + 1], qh[ks][0], qh[ks][1], qh[ks][2], qh[ks][3], bh2, bh3);
                mma_bf16(c_[2 * nbP + 1], qh[ks][0], qh[ks][1], qh[ks][2], qh[ks][3], bl2, bl3);
                mma_bf16(c_[2 * nbP + 1], ql[ks][0], ql[ks][1], ql[ks][2], ql[ks][3], bh2, bh3);
            }
        }

        // ---- commit next tile's panels while QK HMMAs drain ----
        if (t + 1 < ntiles) {
            asm volatile("cp.async.wait_group 0;" ::: "memory");
            commit_tile((t + 1) & 1);
        }

        // ---- softmax chunk interleaved with PV k-step (PV = single fp16 term) ----
        const bool full = (t < 2 * qt);
        const int s0t = t * TKV;
        #pragma unroll
        for (int ks = 0; ks < 4; ks++) {
            uint32_t a0, a1, a2, a3;
            #pragma unroll
            for (int half = 0; half < 2; half++) {
                const int nb = 2 * ks + half;
                float p0, p1, p2, p3;
                if (full) {
                    p0 = exp2f(c_[nb][0] * CEXP);
                    p1 = exp2f(c_[nb][1] * CEXP);
                    p2 = exp2f(c_[nb][2] * CEXP);
                    p3 = exp2f(c_[nb][3] * CEXP);
                } else {
                    const int colA = s0t + nb * 8 + 2 * tig;
                    const int colBc = colA + 1;
                    float s0f = c_[nb][0] * CEXP, s1f = c_[nb][1] * CEXP;
                    float s2f = c_[nb][2] * CEXP, s3f = c_[nb][3] * CEXP;
                    if (drawn) {
                        if (colA == l0)  s0f = dd0s;
                        if (colBc == l0) s1f = dd0s;
                        if (colA == l1)  s2f = dd1s;
                        if (colBc == l1) s3f = dd1s;
                    }
                    p0 = (colA <= l0)  ? exp2f(s0f) : 0.0f;
                    p1 = (colBc <= l0) ? exp2f(s1f) : 0.0f;
                    p2 = (colA <= l1)  ? exp2f(s2f) : 0.0f;
                    p3 = (colBc <= l1) ? exp2f(s3f) : 0.0f;
                    if (drawn) {
                        if (colA == l0)  pd0 = p0;
                        if (colBc == l0) pd0 = p1;
                        if (colA == l1)  pd1 = p2;
                        if (colBc == l1) pd1 = p3;
                    }
                }
                lsum0 += p0 + p1; lsum1 += p2 + p3;
                if (half == 0) { a0 = packh(p0, p1); a1 = packh(p2, p3); }
                else           { a2 = packh(p0, p1); a3 = packh(p2, p3); }
            }
            #pragma unroll
            for (int nbP = 0; nbP < 4; nbP++) {
                uint32_t voff = swz((uint32_t)(ks * 16 + rowV) * 128 + nbP * 32 + colV);
                uint32_t vh0, vh1, vh2, vh3;
                ldsm4t(vh0, vh1, vh2, vh3, vhb + voff);
                mma_f16(o_[2 * nbP],     a0, a1, a2, a3, vh0, vh1);
                mma_f16(o_[2 * nbP + 1], a0, a1, a2, a3, vh2, vh3);
            }
        }

        __syncthreads();
        if (t + 2 < ntiles) prefetch_async(t + 2, t & 1);
    }

    // ---- quad reductions ----
    lsum0 += __shfl_xor_sync(0xffffffffu, lsum0, 1);
    lsum0 += __shfl_xor_sync(0xffffffffu, lsum0, 2);
    lsum1 += __shfl_xor_sync(0xffffffffu, lsum1, 1);
    lsum1 += __shfl_xor_sync(0xffffffffu, lsum1, 2);
    pd0 += __shfl_xor_sync(0xffffffffu, pd0, 1);
    pd0 += __shfl_xor_sync(0xffffffffu, pd0, 2);
    pd1 += __shfl_xor_sync(0xffffffffu, pd1, 1);
    pd1 += __shfl_xor_sync(0xffffffffu, pd1, 2);
    const float inv0 = 1.0f / lsum0;
    const float inv1 = 1.0f / lsum1;

    // ---- epilogue ----
    float* o0p = Out + base + (size_t)l0 * ROWSTRIDE;
    float* o1p = Out + base + (size_t)l1 * ROWSTRIDE;
    if (drawn) {
        const float* v0  = V  + base + (size_t)l0 * ROWSTRIDE;
        const float* vd0 = VD + base + (size_t)l0 * ROWSTRIDE;
        const float* v1  = V  + base + (size_t)l1 * ROWSTRIDE;
        const float* vd1 = VD + base + (size_t)l1 * ROWSTRIDE;
        #pragma unroll
        for (int nb = 0; nb < 8; nb++) {
            int e = nb * 8 + 2 * tig;
            float2 vv = *(const float2*)(v0 + e);
            float2 vd = *(const float2*)(vd0 + e);
            float2 out;
            out.x = (o_[nb][0] + pd0 * (vd.x - vv.x)) * inv0;
            out.y = (o_[nb][1] + pd0 * (vd.y - vv.y)) * inv0;
            *(float2*)(o0p + e) = out;
            float2 vv1  = *(const float2*)(v1 + e);
            float2 vd1v = *(const float2*)(vd1 + e);
            float2 out1;
            out1.x = (o_[nb][2] + pd1 * (vd1v.x - vv1.x)) * inv1;
            out1.y = (o_[nb][3] + pd1 * (vd1v.y - vv1.y)) * inv1;
            *(float2*)(o1p + e) = out1;
        }
    } else {
        #pragma unroll
        for (int nb = 0; nb < 8; nb++) {
            int e = nb * 8 + 2 * tig;
            float2 out;
            out.x = o_[nb][0] * inv0;
            out.y = o_[nb][1] * inv0;
            *(float2*)(o0p + e) = out;
            float2 out1;
            out1.x = o_[nb][2] * inv1;
            out1.y = o_[nb][3] * inv1;
            *(float2*)(o1p + e) = out1;
        }
    }
}

extern "C" void kernel_launch(void* const* d_in, const int* in_sizes, int n_in,
                              void* d_out, int out_size)
{
    const float* Q  = (const float*)d_in[0];
    const float* K  = (const float*)d_in[1];
    const float* V  = (const float*)d_in[2];
    const float* QD = (const float*)d_in[3];
    const float* KD = (const float*)d_in[4];
    const float* VD = (const float*)d_in[5];
    float* O = (float*)d_out;

    static int configured = 0;
    if (!configured) {
        cudaFuncSetAttribute(ftc_attn_mma, cudaFuncAttributeMaxDynamicSharedMemorySize, SMEM_TOTAL);
        configured = 1;
    }
    ftc_attn_mma<<<512, NTHREADS, SMEM_TOTAL>>>(Q, K, V, QD, KD, VD, O);
}